// round 1
// baseline (speedup 1.0000x reference)
#include <cuda_runtime.h>
#include <math.h>

#define BB 32
#define NN 1024
#define FF 10
#define DD 64
#define MM 4
#define RR 8
#define KK 20
#define BN_EPS 1e-5f

// ---------------- scratch (static device arrays; no allocations) ----------------
__device__ float g_h_it [BB*NN*DD];
__device__ float g_xlin [BB*NN*DD];
__device__ float g_eit  [BB*NN];
__device__ float g_hsys [BB*DD];
__device__ float g_pit  [BB*MM];
__device__ float g_mixed[BB*NN*DD];
__device__ float g_si   [BB*NN];
__device__ float g_sj   [BB*NN];
__device__ float g_scores[(size_t)BB*NN*NN];      // 134 MB
__device__ int   g_tidx [BB*NN*KK];
__device__ float g_tw   [BB*NN*KK];
__device__ float g_gnn  [BB*NN*DD];
__device__ float g_out1 [BB*NN*DD];
__device__ float g_part1[128*DD*2];
__device__ float g_part2[128*DD*2];
__device__ float g_scale1[DD], g_shift1[DD], g_scale2[DD], g_shift2[DD];

__device__ __forceinline__ float nanfix(float v) {
    if (isnan(v)) return 0.f;
    if (isinf(v)) return v > 0.f ? 1e4f : -1e4f;
    return v;
}
__device__ __forceinline__ float lrelu(float v) { return v > 0.f ? v : 0.2f * v; }

// ---------------- K1: h_it = data@W_cond+b ; e_it ; x_lin = data@W_gnn ----------
__global__ void __launch_bounds__(256) k1_cond(
    const float* __restrict__ data, const float* __restrict__ Wc,
    const float* __restrict__ bc,   const float* __restrict__ Wap,
    const float* __restrict__ bap,  const float* __restrict__ Wav,
    const float* __restrict__ Wg)
{
    __shared__ float sWc[FF*DD];
    __shared__ float sWap[DD*DD];
    __shared__ float sWg[FF*DD];
    __shared__ float sdata[4][FF];
    __shared__ float sh[4][DD];
    __shared__ float sred[4][2];
    int tid = threadIdx.x;
    for (int i = tid; i < FF*DD; i += 256) { sWc[i] = Wc[i]; sWg[i] = Wg[i]; }
    for (int i = tid; i < DD*DD; i += 256) sWap[i] = Wap[i];
    if (tid < 4*FF) {
        int nd = tid / FF, f = tid % FF;
        int node2 = blockIdx.x * 4 + nd;
        sdata[nd][f] = data[(size_t)node2 * FF + f];
    }
    __syncthreads();
    int grp = tid >> 6, d = tid & 63;
    int node = blockIdx.x * 4 + grp;

    float h = bc[d];
#pragma unroll
    for (int f = 0; f < FF; f++) h += sdata[grp][f] * sWc[f*DD + d];
    sh[grp][d] = h;
    g_h_it[(size_t)node*DD + d] = h;

    float xl = 0.f;
#pragma unroll
    for (int f = 0; f < FF; f++) xl += sdata[grp][f] * sWg[f*DD + d];
    g_xlin[(size_t)node*DD + d] = xl;
    __syncthreads();

    float a = bap[d];
    for (int k = 0; k < DD; k++) a += sh[grp][k] * sWap[k*DD + d];
    a = lrelu(a);
    float ep = a * Wav[d];
    for (int off = 16; off; off >>= 1) ep += __shfl_down_sync(0xffffffffu, ep, off);
    if ((tid & 31) == 0) sred[grp][(tid >> 5) & 1] = ep;
    __syncthreads();
    if (d == 0) g_eit[node] = nanfix(sred[grp][0] + sred[grp][1]);
}

// ---------------- K2: per-batch softmax pool -> h_sys -> gumbel top-2 routing ----
__global__ void __launch_bounds__(256) k2_pool(
    const float* __restrict__ Wr, const float* __restrict__ br,
    const float* __restrict__ gum, float* __restrict__ dout, int out_size)
{
    int b = blockIdx.x, tid = threadIdx.x;
    __shared__ float se[NN];
    __shared__ float sred[8];
    __shared__ float sval;
    __shared__ float spart[4][DD];
    __shared__ float shsys[DD];

    float lmax = -INFINITY;
    for (int n = tid; n < NN; n += 256) { float v = g_eit[b*NN + n]; se[n] = v; lmax = fmaxf(lmax, v); }
    for (int off = 16; off; off >>= 1) lmax = fmaxf(lmax, __shfl_down_sync(0xffffffffu, lmax, off));
    if ((tid & 31) == 0) sred[tid >> 5] = lmax;
    __syncthreads();
    if (tid == 0) { float m = sred[0]; for (int i = 1; i < 8; i++) m = fmaxf(m, sred[i]); sval = m; }
    __syncthreads();
    float mx = sval;
    __syncthreads();
    float lsum = 0.f;
    for (int n = tid; n < NN; n += 256) { float ev = expf(se[n] - mx); se[n] = ev; lsum += ev; }
    for (int off = 16; off; off >>= 1) lsum += __shfl_down_sync(0xffffffffu, lsum, off);
    if ((tid & 31) == 0) sred[tid >> 5] = lsum;
    __syncthreads();
    if (tid == 0) { float s = 0.f; for (int i = 0; i < 8; i++) s += sred[i]; sval = s; }
    __syncthreads();
    float ssum = sval;

    int d = tid & 63, g = tid >> 6;
    float acc = 0.f;
    const float* hb = g_h_it + (size_t)b*NN*DD;
    for (int n = g*256; n < g*256 + 256; n++) acc += se[n] * hb[(size_t)n*DD + d];
    spart[g][d] = acc;
    __syncthreads();
    if (tid < DD) {
        float hs = (spart[0][tid] + spart[1][tid] + spart[2][tid] + spart[3][tid]) / ssum;
        shsys[tid] = hs;
        g_hsys[b*DD + tid] = hs;
        if (out_size >= BB*NN + BB*DD) dout[BB*NN + b*DD + tid] = hs;
    }
    __syncthreads();
    if (tid == 0) {
        float lg[MM]; float pmx = -INFINITY;
        for (int m = 0; m < MM; m++) {
            float s = br[m] + gum[b*MM + m];
            for (int k = 0; k < DD; k++) s += shsys[k] * Wr[k*MM + m];
            lg[m] = s;                  // TAU = 1
            pmx = fmaxf(pmx, s);
        }
        float ps = 0.f;
        for (int m = 0; m < MM; m++) { lg[m] = expf(lg[m] - pmx); ps += lg[m]; }
        float pi[MM];
        for (int m = 0; m < MM; m++) {
            pi[m] = lg[m] / ps;
            if (out_size >= BB*NN + BB*DD + BB*MM)
                dout[BB*NN + BB*DD + b*MM + m] = pi[m];
        }
        // top-2 (ties -> smaller index, matching lax.top_k)
        int i1 = 0;
        for (int m = 1; m < MM; m++) if (pi[m] > pi[i1]) i1 = m;
        int i2 = -1;
        for (int m = 0; m < MM; m++) { if (m == i1) continue; if (i2 < 0 || pi[m] > pi[i2]) i2 = m; }
        float hsum = fmaxf(pi[i1] + pi[i2], 1e-12f);
        for (int m = 0; m < MM; m++)
            g_pit[b*MM + m] = (m == i1 || m == i2) ? pi[m] / hsum : 0.f;
    }
}

// ---------------- K3: mixed = pi_t @ (e_base + lr_u lr_v) ; s_i, s_j ------------
__global__ void __launch_bounds__(256) k3_mixed(
    const float* __restrict__ ebase, const float* __restrict__ lru,
    const float* __restrict__ lrv,
    const float* __restrict__ ai, const float* __restrict__ aj,
    const float* __restrict__ aei, const float* __restrict__ aej)
{
    int b = blockIdx.y;
    int n0 = blockIdx.x * 4;
    __shared__ float sv[MM*RR*DD];
    __shared__ float spi[MM];
    __shared__ float su[4][MM*RR];
    __shared__ float sred[4][2][2];
    int tid = threadIdx.x;
    for (int i = tid; i < MM*RR*DD; i += 256) sv[i] = lrv[i];
    if (tid < MM) spi[tid] = g_pit[b*MM + tid];
    if (tid < 128) {
        int nd = tid >> 5, q = tid & 31;
        int m = q >> 3, r = q & 7;
        su[nd][q] = lru[((size_t)m*NN + (n0 + nd))*RR + r];
    }
    __syncthreads();
    int grp = tid >> 6, d = tid & 63;
    int n = n0 + grp;
    float psum = spi[0] + spi[1] + spi[2] + spi[3];
    float acc = psum * ebase[(size_t)n*DD + d];
#pragma unroll
    for (int m = 0; m < MM; m++) {
        float pm = spi[m];
#pragma unroll
        for (int r = 0; r < RR; r++)
            acc += pm * su[grp][m*RR + r] * sv[(m*RR + r)*DD + d];
    }
    acc = nanfix(acc);
    size_t idx = ((size_t)b*NN + n)*DD + d;
    g_mixed[idx] = acc;
    float xl = g_xlin[idx];
    float t1 = xl*ai[d] + acc*aei[d];
    float t2 = xl*aj[d] + acc*aej[d];
    for (int off = 16; off; off >>= 1) {
        t1 += __shfl_down_sync(0xffffffffu, t1, off);
        t2 += __shfl_down_sync(0xffffffffu, t2, off);
    }
    if ((tid & 31) == 0) {
        int half = (tid >> 5) & 1;
        sred[grp][half][0] = t1;
        sred[grp][half][1] = t2;
    }
    __syncthreads();
    if (d == 0) {
        g_si[b*NN + n] = sred[grp][0][0] + sred[grp][1][0];
        g_sj[b*NN + n] = sred[grp][0][1] + sred[grp][1][1];
    }
}

// ---------------- K4: scores[b] = mixed[b] @ mixed[b]^T  (128x128x64 tiles) -----
__global__ void __launch_bounds__(256) k4_gemm()
{
    extern __shared__ float sm[];
    float* As = sm;                 // [128][65]  (i-major, pad 65 -> conflict-free)
    float* Bs = sm + 128*65;        // [64][132]  (k-major, j contiguous, float4 reads)
    int b  = blockIdx.z;
    int i0 = blockIdx.y * 128, j0 = blockIdx.x * 128;
    const float* A = g_mixed + (size_t)b*NN*DD;
    int tid = threadIdx.x;
    for (int idx = tid; idx < 128*64; idx += 256) {
        int i = idx >> 6, k = idx & 63;
        As[i*65 + k] = A[(size_t)(i0 + i)*DD + k];
    }
    for (int idx = tid; idx < 128*64; idx += 256) {
        int j = idx >> 6, k = idx & 63;
        Bs[k*132 + j] = A[(size_t)(j0 + j)*DD + k];
    }
    __syncthreads();
    int tx = tid & 15, ty = tid >> 4;
    float c[8][8];
#pragma unroll
    for (int r = 0; r < 8; r++)
#pragma unroll
        for (int s = 0; s < 8; s++) c[r][s] = 0.f;

#pragma unroll 8
    for (int k = 0; k < 64; k++) {
        float a[8], bb[8];
#pragma unroll
        for (int r = 0; r < 8; r++) a[r] = As[(ty*8 + r)*65 + k];
        float4 b0 = *(const float4*)&Bs[k*132 + tx*8];
        float4 b1 = *(const float4*)&Bs[k*132 + tx*8 + 4];
        bb[0]=b0.x; bb[1]=b0.y; bb[2]=b0.z; bb[3]=b0.w;
        bb[4]=b1.x; bb[5]=b1.y; bb[6]=b1.z; bb[7]=b1.w;
#pragma unroll
        for (int r = 0; r < 8; r++)
#pragma unroll
            for (int s = 0; s < 8; s++) c[r][s] += a[r] * bb[s];
    }
    float* S = g_scores + (size_t)b*NN*NN;
#pragma unroll
    for (int r = 0; r < 8; r++) {
        float* dst = S + (size_t)(i0 + ty*8 + r)*NN + j0 + tx*8;
        float4 o0 = make_float4(nanfix(c[r][0]), nanfix(c[r][1]), nanfix(c[r][2]), nanfix(c[r][3]));
        float4 o1 = make_float4(nanfix(c[r][4]), nanfix(c[r][5]), nanfix(c[r][6]), nanfix(c[r][7]));
        ((float4*)dst)[0] = o0;
        ((float4*)dst)[1] = o1;
    }
}

// ---------------- K5: per-row top-20 (warp/row) + softmax weights ----------------
__global__ void __launch_bounds__(256) k5_topk()
{
    __shared__ float srow[8][NN];
    int tid = threadIdx.x, w = tid >> 5, lane = tid & 31;
    size_t row = (size_t)blockIdx.x * 8 + w;
    const float* S = g_scores + row * NN;
    float* r = srow[w];
    // lane owns n == lane (mod 32) -> bank-conflict-free, coalesced load
    float mv = -INFINITY; int mi = lane;
    for (int c = 0; c < 32; c++) {
        int n = lane + 32*c;
        float v = S[n];
        r[n] = v;
        if (v > mv) { mv = v; mi = n; }   // first (smallest n) wins ties
    }
    __syncwarp();
    float kv = -INFINITY; int ki = 0;
    for (int t = 0; t < KK; t++) {
        float v = mv; int i = mi;
        for (int off = 16; off; off >>= 1) {
            float ov = __shfl_down_sync(0xffffffffu, v, off);
            int   oi = __shfl_down_sync(0xffffffffu, i, off);
            if (ov > v || (ov == v && oi < i)) { v = ov; i = oi; }
        }
        float bv = __shfl_sync(0xffffffffu, v, 0);
        int   bi = __shfl_sync(0xffffffffu, i, 0);
        if (lane == t) { kv = bv; ki = bi; }
        if ((bi & 31) == lane) {
            r[bi] = -INFINITY;
            mv = -INFINITY; mi = lane;
            for (int c = 0; c < 32; c++) {
                int n = lane + 32*c;
                float vv = r[n];
                if (vv > mv) { mv = vv; mi = n; }
            }
        }
    }
    // softmax over the 20 values
    float val = (lane < KK) ? kv : -INFINITY;
    float m2 = val;
    for (int off = 16; off; off >>= 1) m2 = fmaxf(m2, __shfl_xor_sync(0xffffffffu, m2, off));
    float e = (lane < KK) ? expf(val - m2) : 0.f;
    float s2 = e;
    for (int off = 16; off; off >>= 1) s2 += __shfl_xor_sync(0xffffffffu, s2, off);
    if (lane < KK) {
        g_tidx[row*KK + lane] = ki;
        g_tw[row*KK + lane]   = e / s2;
    }
}

// ---------------- K6: GAT edge softmax + weighted aggregation (warp/node) --------
__global__ void __launch_bounds__(256) k6_gat(const float* __restrict__ bgnn)
{
    int tid = threadIdx.x, w = tid >> 5, lane = tid & 31;
    int row = blockIdx.x * 8 + w;
    int b = row >> 10, n = row & (NN - 1);
    float si  = g_si[row];
    float sjn = g_sj[row];
    int idx = 0; float tw = 0.f, alpha = -INFINITY;
    if (lane < KK) {
        idx = g_tidx[(size_t)row*KK + lane];
        tw  = g_tw[(size_t)row*KK + lane];
        float sj = g_sj[b*NN + idx];
        if (idx != n) alpha = lrelu(si + sj);         // self-loop removed
    } else if (lane == KK) {
        alpha = lrelu(si + sjn);                      // re-added self loop
    }
    float m = alpha;
    for (int off = 16; off; off >>= 1) m = fmaxf(m, __shfl_xor_sync(0xffffffffu, m, off));
    float e = (lane <= KK) ? expf(alpha - m) : 0.f;
    float s = e;
    for (int off = 16; off; off >>= 1) s += __shfl_xor_sync(0xffffffffu, s, off);
    float wgt = e / s;
    if (lane < KK) wgt *= tw;

    size_t xb = (size_t)b*NN*DD;
    float ws = __shfl_sync(0xffffffffu, wgt, KK);
    float a0 = ws * g_xlin[(size_t)row*DD + lane];
    float a1 = ws * g_xlin[(size_t)row*DD + lane + 32];
#pragma unroll
    for (int k = 0; k < KK; k++) {
        float wk = __shfl_sync(0xffffffffu, wgt, k);
        int   ik = __shfl_sync(0xffffffffu, idx, k);
        const float* xr = g_xlin + xb + (size_t)ik*DD;
        a0 += wk * xr[lane];
        a1 += wk * xr[lane + 32];
    }
    g_gnn[(size_t)row*DD + lane]      = a0 + bgnn[lane];
    g_gnn[(size_t)row*DD + lane + 32] = a1 + bgnn[lane + 32];
}

// ---------------- K7: partial per-channel stats of g_gnn -------------------------
__global__ void __launch_bounds__(256) k7_stats()
{
    int tid = threadIdx.x, d = tid & 63, g = tid >> 6;
    size_t r0 = (size_t)blockIdx.x * 256 + g * 64;
    float s = 0.f, q = 0.f;
    for (int r = 0; r < 64; r++) {
        float v = g_gnn[(r0 + r)*DD + d];
        s += v; q += v*v;
    }
    __shared__ float ss[4][DD], sq[4][DD];
    ss[g][d] = s; sq[g][d] = q;
    __syncthreads();
    if (tid < DD) {
        g_part1[blockIdx.x*DD*2 + tid]      = ss[0][tid]+ss[1][tid]+ss[2][tid]+ss[3][tid];
        g_part1[blockIdx.x*DD*2 + DD + tid] = sq[0][tid]+sq[1][tid]+sq[2][tid]+sq[3][tid];
    }
}

// ---------------- K8: fold partials -> scale/shift (which: 0 = bn1, 1 = bn_out) --
__global__ void k8_bnparam(int which, const float* __restrict__ gamma,
                           const float* __restrict__ beta)
{
    int d = threadIdx.x;
    if (d >= DD) return;
    const float* part = which ? g_part2 : g_part1;
    float s = 0.f, q = 0.f;
    for (int i = 0; i < 128; i++) {
        s += part[i*DD*2 + d];
        q += part[i*DD*2 + DD + d];
    }
    float inv = 1.f / (float)(BB*NN);
    float mean = s * inv;
    float var  = q * inv - mean*mean;
    float sc = gamma[d] * rsqrtf(var + BN_EPS);
    if (which) { g_scale2[d] = sc; g_shift2[d] = beta[d] - mean*sc; }
    else       { g_scale1[d] = sc; g_shift1[d] = beta[d] - mean*sc; }
}

// ---------------- K9: bn1+relu, *embed -> out1, partial stats2 -------------------
__global__ void __launch_bounds__(256) k9_mid(const float* __restrict__ embed)
{
    int tid = threadIdx.x, d = tid & 63, g = tid >> 6;
    size_t r0 = (size_t)blockIdx.x * 256 + g * 64;
    float sc = g_scale1[d], sh = g_shift1[d];
    float s = 0.f, q = 0.f;
    for (int r = 0; r < 64; r++) {
        size_t row = r0 + r;
        int n = (int)(row & (NN - 1));
        float v = fmaxf(g_gnn[row*DD + d]*sc + sh, 0.f);
        float o = v * embed[(size_t)n*DD + d];
        g_out1[row*DD + d] = o;
        s += o; q += o*o;
    }
    __shared__ float ss[4][DD], sq[4][DD];
    ss[g][d] = s; sq[g][d] = q;
    __syncthreads();
    if (tid < DD) {
        g_part2[blockIdx.x*DD*2 + tid]      = ss[0][tid]+ss[1][tid]+ss[2][tid]+ss[3][tid];
        g_part2[blockIdx.x*DD*2 + DD + tid] = sq[0][tid]+sq[1][tid]+sq[2][tid]+sq[3][tid];
    }
}

// ---------------- K11: bn_out+relu, @W_out + b_out -> out[b,n] -------------------
__global__ void __launch_bounds__(256) k11_out(
    const float* __restrict__ Wout, const float* __restrict__ bout,
    float* __restrict__ dout, int out_size)
{
    int tid = threadIdx.x, w = tid >> 5, lane = tid & 31;
    int row = blockIdx.x * 8 + w;
    float v0 = fmaxf(g_out1[(size_t)row*DD + lane]     *g_scale2[lane]      + g_shift2[lane],      0.f)*Wout[lane];
    float v1 = fmaxf(g_out1[(size_t)row*DD + lane + 32]*g_scale2[lane + 32] + g_shift2[lane + 32], 0.f)*Wout[lane + 32];
    float s = v0 + v1;
    for (int off = 16; off; off >>= 1) s += __shfl_down_sync(0xffffffffu, s, off);
    if (lane == 0 && row < out_size) dout[row] = s + bout[0];
}

// ---------------- launch --------------------------------------------------------
extern "C" void kernel_launch(void* const* d_in, const int* in_sizes, int n_in,
                              void* d_out, int out_size)
{
    const float* data = (const float*)d_in[0];
    const float* gum  = (const float*)d_in[1];
    const float* Wc   = (const float*)d_in[2];
    const float* bc   = (const float*)d_in[3];
    const float* Wap  = (const float*)d_in[4];
    const float* bap  = (const float*)d_in[5];
    const float* Wav  = (const float*)d_in[6];
    const float* Wr   = (const float*)d_in[7];
    const float* br   = (const float*)d_in[8];
    const float* eb   = (const float*)d_in[9];
    const float* lru  = (const float*)d_in[10];
    const float* lrv  = (const float*)d_in[11];
    const float* Wg   = (const float*)d_in[12];
    const float* ai   = (const float*)d_in[13];
    const float* aj   = (const float*)d_in[14];
    const float* aei  = (const float*)d_in[15];
    const float* aej  = (const float*)d_in[16];
    const float* bgnn = (const float*)d_in[17];
    const float* g1   = (const float*)d_in[18];
    const float* be1  = (const float*)d_in[19];
    const float* emb  = (const float*)d_in[20];
    const float* g2   = (const float*)d_in[21];
    const float* be2  = (const float*)d_in[22];
    const float* Wout = (const float*)d_in[23];
    const float* bout = (const float*)d_in[24];
    float* out = (float*)d_out;

    k1_cond<<<BB*NN/4, 256>>>(data, Wc, bc, Wap, bap, Wav, Wg);
    k2_pool<<<BB, 256>>>(Wr, br, gum, out, out_size);
    dim3 g3(NN/4, BB);
    k3_mixed<<<g3, 256>>>(eb, lru, lrv, ai, aj, aei, aej);

    const int k4_smem = (128*65 + 64*132) * 4;   // 67072 B
    cudaFuncSetAttribute((const void*)k4_gemm,
                         cudaFuncAttributeMaxDynamicSharedMemorySize, k4_smem);
    dim3 g4(NN/128, NN/128, BB);
    k4_gemm<<<g4, 256, k4_smem>>>();

    k5_topk<<<BB*NN/8, 256>>>();
    k6_gat<<<BB*NN/8, 256>>>(bgnn);
    k7_stats<<<128, 256>>>();
    k8_bnparam<<<1, 64>>>(0, g1, be1);
    k9_mid<<<128, 256>>>(emb);
    k8_bnparam<<<1, 64>>>(1, g2, be2);
    k11_out<<<BB*NN/8, 256>>>(Wout, bout, out, out_size);
}

// round 2
// speedup vs baseline: 1.4466x; 1.4466x over previous
#include <cuda_runtime.h>
#include <math.h>

#define BB 32
#define NN 1024
#define FF 10
#define DD 64
#define MM 4
#define RR 8
#define KK 20
#define BN_EPS 1e-5f

// ---------------- scratch (static device arrays; no allocations) ----------------
__device__ float g_h_it [BB*NN*DD];
__device__ float g_xlin [BB*NN*DD];
__device__ float g_eit  [BB*NN];
__device__ float g_mixed[BB*NN*DD];
__device__ float g_si   [BB*NN];
__device__ float g_sj   [BB*NN];
__device__ float g_proto[MM*NN*DD];                 // P_m = e_base + U_m V_m
__device__ float g_gram [(size_t)10*NN*NN];         // 40 MB: 4 diag G_mm + 6 sym H_ml
__device__ int   g_cmb_i[BB*5];                     // {a, b, id_aa, id_bb, id_ab}
__device__ float g_cmb_f[BB*5];                     // {ca, cb, ca^2, cb^2, ca*cb}
__device__ int   g_tidx [BB*NN*KK];
__device__ float g_tw   [BB*NN*KK];
__device__ float g_gnn  [BB*NN*DD];
__device__ float g_out1 [BB*NN*DD];
__device__ float g_part1[128*DD*2];
__device__ float g_part2[128*DD*2];
__device__ float g_scale1[DD], g_shift1[DD], g_scale2[DD], g_shift2[DD];

__device__ const int c_pm[10] = {0,0,0,0,1,1,1,2,2,3};
__device__ const int c_pl[10] = {0,1,2,3,1,2,3,2,3,3};

__device__ __forceinline__ float nanfix(float v) {
    if (isnan(v)) return 0.f;
    if (isinf(v)) return v > 0.f ? 1e4f : -1e4f;
    return v;
}
__device__ __forceinline__ float lrelu(float v) { return v > 0.f ? v : 0.2f * v; }
// order-preserving float <-> uint bijection (no NaN inputs)
__device__ __forceinline__ unsigned ordf(float f) {
    unsigned u = __float_as_uint(f);
    return (u & 0x80000000u) ? ~u : (u | 0x80000000u);
}
__device__ __forceinline__ float unordf(unsigned o) {
    unsigned u = (o & 0x80000000u) ? (o & 0x7fffffffu) : ~o;
    return __uint_as_float(u);
}
__device__ __forceinline__ int pidf(int m, int l) { return m*4 + l - (m*(m+1))/2; }

// ---------------- kP: proto P[m] = e_base + U_m V_m ------------------------------
__global__ void __launch_bounds__(256) kP_proto(
    const float* __restrict__ eb, const float* __restrict__ lru,
    const float* __restrict__ lrv)
{
    int m = blockIdx.y, n0 = blockIdx.x * 4;
    __shared__ float sv[RR*DD];
    __shared__ float su[4][RR];
    int tid = threadIdx.x;
    for (int i = tid; i < RR*DD; i += 256) sv[i] = lrv[(size_t)m*RR*DD + i];
    if (tid < 32) {
        int nd = tid >> 3, r = tid & 7;
        su[nd][r] = lru[((size_t)m*NN + n0 + nd)*RR + r];
    }
    __syncthreads();
    int grp = tid >> 6, d = tid & 63;
    int n = n0 + grp;
    float acc = eb[(size_t)n*DD + d];
#pragma unroll
    for (int r = 0; r < RR; r++) acc += su[grp][r] * sv[r*DD + d];
    g_proto[((size_t)m*NN + n)*DD + d] = acc;
}

// ---------------- K1: h_it = data@W_cond+b ; e_it ; x_lin = data@W_gnn ----------
__global__ void __launch_bounds__(256) k1_cond(
    const float* __restrict__ data, const float* __restrict__ Wc,
    const float* __restrict__ bc,   const float* __restrict__ Wap,
    const float* __restrict__ bap,  const float* __restrict__ Wav,
    const float* __restrict__ Wg)
{
    __shared__ float sWc[FF*DD];
    __shared__ float sWap[DD*DD];
    __shared__ float sWg[FF*DD];
    __shared__ float sdata[4][FF];
    __shared__ float sh[4][DD];
    __shared__ float sred[4][2];
    int tid = threadIdx.x;
    for (int i = tid; i < FF*DD; i += 256) { sWc[i] = Wc[i]; sWg[i] = Wg[i]; }
    for (int i = tid; i < DD*DD; i += 256) sWap[i] = Wap[i];
    if (tid < 4*FF) {
        int nd = tid / FF, f = tid % FF;
        int node2 = blockIdx.x * 4 + nd;
        sdata[nd][f] = data[(size_t)node2 * FF + f];
    }
    __syncthreads();
    int grp = tid >> 6, d = tid & 63;
    int node = blockIdx.x * 4 + grp;

    float h = bc[d];
#pragma unroll
    for (int f = 0; f < FF; f++) h += sdata[grp][f] * sWc[f*DD + d];
    sh[grp][d] = h;
    g_h_it[(size_t)node*DD + d] = h;

    float xl = 0.f;
#pragma unroll
    for (int f = 0; f < FF; f++) xl += sdata[grp][f] * sWg[f*DD + d];
    g_xlin[(size_t)node*DD + d] = xl;
    __syncthreads();

    float a = bap[d];
    for (int k = 0; k < DD; k++) a += sh[grp][k] * sWap[k*DD + d];
    a = lrelu(a);
    float ep = a * Wav[d];
    for (int off = 16; off; off >>= 1) ep += __shfl_down_sync(0xffffffffu, ep, off);
    if ((tid & 31) == 0) sred[grp][(tid >> 5) & 1] = ep;
    __syncthreads();
    if (d == 0) g_eit[node] = nanfix(sred[grp][0] + sred[grp][1]);
}

// ---------------- K2: per-batch pool -> h_sys -> gumbel top-2 routing -----------
__global__ void __launch_bounds__(256) k2_pool(
    const float* __restrict__ Wr, const float* __restrict__ br,
    const float* __restrict__ gum, float* __restrict__ dout, int out_size)
{
    int b = blockIdx.x, tid = threadIdx.x;
    __shared__ float se[NN];
    __shared__ float sred[8];
    __shared__ float sval;
    __shared__ float spart[4][DD];
    __shared__ float shsys[DD];

    float lmax = -INFINITY;
    for (int n = tid; n < NN; n += 256) { float v = g_eit[b*NN + n]; se[n] = v; lmax = fmaxf(lmax, v); }
    for (int off = 16; off; off >>= 1) lmax = fmaxf(lmax, __shfl_down_sync(0xffffffffu, lmax, off));
    if ((tid & 31) == 0) sred[tid >> 5] = lmax;
    __syncthreads();
    if (tid == 0) { float m = sred[0]; for (int i = 1; i < 8; i++) m = fmaxf(m, sred[i]); sval = m; }
    __syncthreads();
    float mx = sval;
    __syncthreads();
    float lsum = 0.f;
    for (int n = tid; n < NN; n += 256) { float ev = expf(se[n] - mx); se[n] = ev; lsum += ev; }
    for (int off = 16; off; off >>= 1) lsum += __shfl_down_sync(0xffffffffu, lsum, off);
    if ((tid & 31) == 0) sred[tid >> 5] = lsum;
    __syncthreads();
    if (tid == 0) { float s = 0.f; for (int i = 0; i < 8; i++) s += sred[i]; sval = s; }
    __syncthreads();
    float ssum = sval;

    int d = tid & 63, g = tid >> 6;
    float acc = 0.f;
    const float* hb = g_h_it + (size_t)b*NN*DD;
    for (int n = g*256; n < g*256 + 256; n++) acc += se[n] * hb[(size_t)n*DD + d];
    spart[g][d] = acc;
    __syncthreads();
    if (tid < DD) {
        float hs = (spart[0][tid] + spart[1][tid] + spart[2][tid] + spart[3][tid]) / ssum;
        shsys[tid] = hs;
        if (out_size >= BB*NN + BB*DD) dout[BB*NN + b*DD + tid] = hs;
    }
    __syncthreads();
    if (tid == 0) {
        float lg[MM]; float pmx = -INFINITY;
        for (int m = 0; m < MM; m++) {
            float s = br[m] + gum[b*MM + m];
            for (int k = 0; k < DD; k++) s += shsys[k] * Wr[k*MM + m];
            lg[m] = s;                  // TAU = 1
            pmx = fmaxf(pmx, s);
        }
        float ps = 0.f;
        for (int m = 0; m < MM; m++) { lg[m] = expf(lg[m] - pmx); ps += lg[m]; }
        float pi[MM];
        for (int m = 0; m < MM; m++) {
            pi[m] = lg[m] / ps;
            if (out_size >= BB*NN + BB*DD + BB*MM)
                dout[BB*NN + BB*DD + b*MM + m] = pi[m];
        }
        // top-2 (ties -> smaller index, matching lax.top_k)
        int i1 = 0;
        for (int m = 1; m < MM; m++) if (pi[m] > pi[i1]) i1 = m;
        int i2 = -1;
        for (int m = 0; m < MM; m++) { if (m == i1) continue; if (i2 < 0 || pi[m] > pi[i2]) i2 = m; }
        float hsum = fmaxf(pi[i1] + pi[i2], 1e-12f);
        int a  = i1 < i2 ? i1 : i2;
        int b2 = i1 < i2 ? i2 : i1;
        float ca = pi[a] / hsum, cb = pi[b2] / hsum;
        g_cmb_i[b*5+0] = a;            g_cmb_i[b*5+1] = b2;
        g_cmb_i[b*5+2] = pidf(a, a);   g_cmb_i[b*5+3] = pidf(b2, b2);
        g_cmb_i[b*5+4] = pidf(a, b2);
        g_cmb_f[b*5+0] = ca;   g_cmb_f[b*5+1] = cb;
        g_cmb_f[b*5+2] = ca*ca; g_cmb_f[b*5+3] = cb*cb; g_cmb_f[b*5+4] = ca*cb;
    }
}

// ---------------- K3: mixed = ca*P_a + cb*P_b ; s_i, s_j -------------------------
__global__ void __launch_bounds__(256) k3_mixed(
    const float* __restrict__ ai, const float* __restrict__ aj,
    const float* __restrict__ aei, const float* __restrict__ aej)
{
    int b = blockIdx.y;
    int n0 = blockIdx.x * 4;
    __shared__ float sred[4][2][2];
    int tid = threadIdx.x;
    int grp = tid >> 6, d = tid & 63;
    int ea = g_cmb_i[b*5+0], eb2 = g_cmb_i[b*5+1];
    float ca = g_cmb_f[b*5+0], cb = g_cmb_f[b*5+1];
    int n = n0 + grp;
    float acc = nanfix(ca * g_proto[((size_t)ea*NN + n)*DD + d]
                     + cb * g_proto[((size_t)eb2*NN + n)*DD + d]);
    size_t idx = ((size_t)b*NN + n)*DD + d;
    g_mixed[idx] = acc;
    float xl = g_xlin[idx];
    float t1 = xl*ai[d] + acc*aei[d];
    float t2 = xl*aj[d] + acc*aej[d];
    for (int off = 16; off; off >>= 1) {
        t1 += __shfl_down_sync(0xffffffffu, t1, off);
        t2 += __shfl_down_sync(0xffffffffu, t2, off);
    }
    if ((tid & 31) == 0) {
        int half = (tid >> 5) & 1;
        sred[grp][half][0] = t1;
        sred[grp][half][1] = t2;
    }
    __syncthreads();
    if (d == 0) {
        g_si[b*NN + n] = sred[grp][0][0] + sred[grp][1][0];
        g_sj[b*NN + n] = sred[grp][0][1] + sred[grp][1][1];
    }
}

// ---------------- kB: Gram matrices. diag: G_mm ; cross: H_ml = G_ml + G_ml^T ----
__global__ void __launch_bounds__(256) kB_gram()
{
    extern __shared__ float sm[];
    float* As = sm;                 // [128][65]
    float* Bs = sm + 128*65;        // [64][132]
    int pid = blockIdx.z;
    int m = c_pm[pid], l = c_pl[pid];
    int i0 = blockIdx.y * 128, j0 = blockIdx.x * 128;
    int tid = threadIdx.x;
    int tx = tid & 15, ty = tid >> 4;
    float c[8][8];
#pragma unroll
    for (int r = 0; r < 8; r++)
#pragma unroll
        for (int s = 0; s < 8; s++) c[r][s] = 0.f;

    int npass = (m == l) ? 1 : 2;
    for (int p = 0; p < npass; p++) {
        const float* A  = g_proto + (size_t)(p == 0 ? m : l)*NN*DD;
        const float* Bv = g_proto + (size_t)(p == 0 ? l : m)*NN*DD;
        if (p) __syncthreads();
        for (int idx = tid; idx < 128*64; idx += 256) {
            int i = idx >> 6, k = idx & 63;
            As[i*65 + k] = A[(size_t)(i0 + i)*DD + k];
        }
        for (int idx = tid; idx < 128*64; idx += 256) {
            int j = idx >> 6, k = idx & 63;
            Bs[k*132 + j] = Bv[(size_t)(j0 + j)*DD + k];
        }
        __syncthreads();
#pragma unroll 8
        for (int k = 0; k < 64; k++) {
            float a[8], bb[8];
#pragma unroll
            for (int r = 0; r < 8; r++) a[r] = As[(ty*8 + r)*65 + k];
            float4 b0 = *(const float4*)&Bs[k*132 + tx*8];
            float4 b1 = *(const float4*)&Bs[k*132 + tx*8 + 4];
            bb[0]=b0.x; bb[1]=b0.y; bb[2]=b0.z; bb[3]=b0.w;
            bb[4]=b1.x; bb[5]=b1.y; bb[6]=b1.z; bb[7]=b1.w;
#pragma unroll
            for (int r = 0; r < 8; r++)
#pragma unroll
                for (int s = 0; s < 8; s++) c[r][s] += a[r] * bb[s];
        }
    }
    float* G = g_gram + (size_t)pid*NN*NN;
#pragma unroll
    for (int r = 0; r < 8; r++) {
        float* dst = G + (size_t)(i0 + ty*8 + r)*NN + j0 + tx*8;
        ((float4*)dst)[0] = make_float4(c[r][0], c[r][1], c[r][2], c[r][3]);
        ((float4*)dst)[1] = make_float4(c[r][4], c[r][5], c[r][6], c[r][7]);
    }
}

// ---------------- kC: fused score-combine + exact top-20 + softmax (warp/row) ----
__global__ void __launch_bounds__(256) kC_topk()
{
    int tid = threadIdx.x, w = tid >> 5, lane = tid & 31;
    int row = blockIdx.x * 8 + w;
    int b = row >> 10, i = row & (NN - 1);
    int ida = g_cmb_i[b*5+2], idb = g_cmb_i[b*5+3], idh = g_cmb_i[b*5+4];
    float caa = g_cmb_f[b*5+2], cbb = g_cmb_f[b*5+3], cab = g_cmb_f[b*5+4];
    const float* ga = g_gram + ((size_t)ida << 20) + ((size_t)i << 10);
    const float* gb = g_gram + ((size_t)idb << 20) + ((size_t)i << 10);
    const float* gh = g_gram + ((size_t)idh << 20) + ((size_t)i << 10);

    // lane owns 32 values: n = 128*cc + 4*lane + q  (float4-coalesced)
    unsigned ov[32];
#pragma unroll
    for (int cc = 0; cc < 8; cc++) {
        int off = cc*128 + lane*4;
        float4 x = *(const float4*)(ga + off);
        float4 y = *(const float4*)(gb + off);
        float4 z = *(const float4*)(gh + off);
        ov[cc*4+0] = ordf(nanfix(caa*x.x + cbb*y.x + cab*z.x));
        ov[cc*4+1] = ordf(nanfix(caa*x.y + cbb*y.y + cab*z.y));
        ov[cc*4+2] = ordf(nanfix(caa*x.z + cbb*y.z + cab*z.z));
        ov[cc*4+3] = ordf(nanfix(caa*x.w + cbb*y.w + cab*z.w));
    }
    // 4 groups of 8; ascending scan + strict '>' keeps smallest local index on ties
    unsigned gm[4]; int gi[4];
#pragma unroll
    for (int g = 0; g < 4; g++) {
        unsigned bm = 0; int bi = g*8;
#pragma unroll
        for (int q = 0; q < 8; q++) {
            int li = g*8 + q;
            if (ov[li] > bm) { bm = ov[li]; bi = li; }
        }
        gm[g] = bm; gi[g] = bi;
    }

    unsigned res_o = 0; int res_n = 0;
#pragma unroll 1
    for (int t = 0; t < KK; t++) {
        unsigned lv = gm[0]; int lg = 0;
        if (gm[1] > lv) { lv = gm[1]; lg = 1; }
        if (gm[2] > lv) { lv = gm[2]; lg = 2; }
        if (gm[3] > lv) { lv = gm[3]; lg = 3; }
        int li = (lg == 0) ? gi[0] : (lg == 1) ? gi[1] : (lg == 2) ? gi[2] : gi[3];
        int my_n = ((li >> 2) << 7) + (lane << 2) + (li & 3);
        unsigned wv = __reduce_max_sync(0xffffffffu, lv);
        unsigned cand = (lv == wv) ? (unsigned)my_n : 0xffffffffu;
        unsigned wn = __reduce_min_sync(0xffffffffu, cand);
        if (lane == t) { res_o = wv; res_n = (int)wn; }
        if (lv == wv && (unsigned)my_n == wn) {
            // pop li, rescan only its 8-element group
#pragma unroll
            for (int g = 0; g < 4; g++) if (lg == g) {
                unsigned bm = 0; int bi = g*8;
#pragma unroll
                for (int q = 0; q < 8; q++) {
                    int l2 = g*8 + q;
                    if (l2 == li) ov[l2] = 0;
                    if (ov[l2] > bm) { bm = ov[l2]; bi = l2; }
                }
                gm[g] = bm; gi[g] = bi;
            }
        }
    }
    // softmax over the 20 extracted values
    float val = (lane < KK) ? unordf(res_o) : -INFINITY;
    float m2 = val;
    for (int off = 16; off; off >>= 1) m2 = fmaxf(m2, __shfl_xor_sync(0xffffffffu, m2, off));
    float e = (lane < KK) ? expf(val - m2) : 0.f;
    float s2 = e;
    for (int off = 16; off; off >>= 1) s2 += __shfl_xor_sync(0xffffffffu, s2, off);
    if (lane < KK) {
        g_tidx[(size_t)row*KK + lane] = res_n;
        g_tw[(size_t)row*KK + lane]   = e / s2;
    }
}

// ---------------- K6: GAT edge softmax + weighted aggregation (warp/node) --------
__global__ void __launch_bounds__(256) k6_gat(const float* __restrict__ bgnn)
{
    int tid = threadIdx.x, w = tid >> 5, lane = tid & 31;
    int row = blockIdx.x * 8 + w;
    int b = row >> 10, n = row & (NN - 1);
    float si  = g_si[row];
    float sjn = g_sj[row];
    int idx = 0; float tw = 0.f, alpha = -INFINITY;
    if (lane < KK) {
        idx = g_tidx[(size_t)row*KK + lane];
        tw  = g_tw[(size_t)row*KK + lane];
        float sj = g_sj[b*NN + idx];
        if (idx != n) alpha = lrelu(si + sj);         // self-loop removed
    } else if (lane == KK) {
        alpha = lrelu(si + sjn);                      // re-added self loop
    }
    float m = alpha;
    for (int off = 16; off; off >>= 1) m = fmaxf(m, __shfl_xor_sync(0xffffffffu, m, off));
    float e = (lane <= KK) ? expf(alpha - m) : 0.f;
    float s = e;
    for (int off = 16; off; off >>= 1) s += __shfl_xor_sync(0xffffffffu, s, off);
    float wgt = e / s;
    if (lane < KK) wgt *= tw;

    size_t xb = (size_t)b*NN*DD;
    float ws = __shfl_sync(0xffffffffu, wgt, KK);
    float a0 = ws * g_xlin[(size_t)row*DD + lane];
    float a1 = ws * g_xlin[(size_t)row*DD + lane + 32];
#pragma unroll
    for (int k = 0; k < KK; k++) {
        float wk = __shfl_sync(0xffffffffu, wgt, k);
        int   ik = __shfl_sync(0xffffffffu, idx, k);
        const float* xr = g_xlin + xb + (size_t)ik*DD;
        a0 += wk * xr[lane];
        a1 += wk * xr[lane + 32];
    }
    g_gnn[(size_t)row*DD + lane]      = a0 + bgnn[lane];
    g_gnn[(size_t)row*DD + lane + 32] = a1 + bgnn[lane + 32];
}

// ---------------- K7: partial per-channel stats of g_gnn -------------------------
__global__ void __launch_bounds__(256) k7_stats()
{
    int tid = threadIdx.x, d = tid & 63, g = tid >> 6;
    size_t r0 = (size_t)blockIdx.x * 256 + g * 64;
    float s = 0.f, q = 0.f;
    for (int r = 0; r < 64; r++) {
        float v = g_gnn[(r0 + r)*DD + d];
        s += v; q += v*v;
    }
    __shared__ float ss[4][DD], sq[4][DD];
    ss[g][d] = s; sq[g][d] = q;
    __syncthreads();
    if (tid < DD) {
        g_part1[blockIdx.x*DD*2 + tid]      = ss[0][tid]+ss[1][tid]+ss[2][tid]+ss[3][tid];
        g_part1[blockIdx.x*DD*2 + DD + tid] = sq[0][tid]+sq[1][tid]+sq[2][tid]+sq[3][tid];
    }
}

// ---------------- K8: fold partials -> scale/shift (which: 0 = bn1, 1 = bn_out) --
__global__ void k8_bnparam(int which, const float* __restrict__ gamma,
                           const float* __restrict__ beta)
{
    int d = threadIdx.x;
    if (d >= DD) return;
    const float* part = which ? g_part2 : g_part1;
    float s = 0.f, q = 0.f;
    for (int i = 0; i < 128; i++) {
        s += part[i*DD*2 + d];
        q += part[i*DD*2 + DD + d];
    }
    float inv = 1.f / (float)(BB*NN);
    float mean = s * inv;
    float var  = q * inv - mean*mean;
    float sc = gamma[d] * rsqrtf(var + BN_EPS);
    if (which) { g_scale2[d] = sc; g_shift2[d] = beta[d] - mean*sc; }
    else       { g_scale1[d] = sc; g_shift1[d] = beta[d] - mean*sc; }
}

// ---------------- K9: bn1+relu, *embed -> out1, partial stats2 -------------------
__global__ void __launch_bounds__(256) k9_mid(const float* __restrict__ embed)
{
    int tid = threadIdx.x, d = tid & 63, g = tid >> 6;
    size_t r0 = (size_t)blockIdx.x * 256 + g * 64;
    float sc = g_scale1[d], sh = g_shift1[d];
    float s = 0.f, q = 0.f;
    for (int r = 0; r < 64; r++) {
        size_t row = r0 + r;
        int n = (int)(row & (NN - 1));
        float v = fmaxf(g_gnn[row*DD + d]*sc + sh, 0.f);
        float o = v * embed[(size_t)n*DD + d];
        g_out1[row*DD + d] = o;
        s += o; q += o*o;
    }
    __shared__ float ss[4][DD], sq[4][DD];
    ss[g][d] = s; sq[g][d] = q;
    __syncthreads();
    if (tid < DD) {
        g_part2[blockIdx.x*DD*2 + tid]      = ss[0][tid]+ss[1][tid]+ss[2][tid]+ss[3][tid];
        g_part2[blockIdx.x*DD*2 + DD + tid] = sq[0][tid]+sq[1][tid]+sq[2][tid]+sq[3][tid];
    }
}

// ---------------- K11: bn_out+relu, @W_out + b_out -> out[b,n] -------------------
__global__ void __launch_bounds__(256) k11_out(
    const float* __restrict__ Wout, const float* __restrict__ bout,
    float* __restrict__ dout, int out_size)
{
    int tid = threadIdx.x, w = tid >> 5, lane = tid & 31;
    int row = blockIdx.x * 8 + w;
    float v0 = fmaxf(g_out1[(size_t)row*DD + lane]     *g_scale2[lane]      + g_shift2[lane],      0.f)*Wout[lane];
    float v1 = fmaxf(g_out1[(size_t)row*DD + lane + 32]*g_scale2[lane + 32] + g_shift2[lane + 32], 0.f)*Wout[lane + 32];
    float s = v0 + v1;
    for (int off = 16; off; off >>= 1) s += __shfl_down_sync(0xffffffffu, s, off);
    if (lane == 0 && row < out_size) dout[row] = s + bout[0];
}

// ---------------- launch --------------------------------------------------------
extern "C" void kernel_launch(void* const* d_in, const int* in_sizes, int n_in,
                              void* d_out, int out_size)
{
    const float* data = (const float*)d_in[0];
    const float* gum  = (const float*)d_in[1];
    const float* Wc   = (const float*)d_in[2];
    const float* bc   = (const float*)d_in[3];
    const float* Wap  = (const float*)d_in[4];
    const float* bap  = (const float*)d_in[5];
    const float* Wav  = (const float*)d_in[6];
    const float* Wr   = (const float*)d_in[7];
    const float* br   = (const float*)d_in[8];
    const float* eb   = (const float*)d_in[9];
    const float* lru  = (const float*)d_in[10];
    const float* lrv  = (const float*)d_in[11];
    // d_in[12] = W_gnn handled in k1
    const float* Wg   = (const float*)d_in[12];
    const float* ai   = (const float*)d_in[13];
    const float* aj   = (const float*)d_in[14];
    const float* aei  = (const float*)d_in[15];
    const float* aej  = (const float*)d_in[16];
    const float* bgnn = (const float*)d_in[17];
    const float* g1   = (const float*)d_in[18];
    const float* be1  = (const float*)d_in[19];
    const float* emb  = (const float*)d_in[20];
    const float* g2   = (const float*)d_in[21];
    const float* be2  = (const float*)d_in[22];
    const float* Wout = (const float*)d_in[23];
    const float* bout = (const float*)d_in[24];
    float* out = (float*)d_out;

    dim3 gp(NN/4, MM);
    kP_proto<<<gp, 256>>>(eb, lru, lrv);
    k1_cond<<<BB*NN/4, 256>>>(data, Wc, bc, Wap, bap, Wav, Wg);
    k2_pool<<<BB, 256>>>(Wr, br, gum, out, out_size);
    dim3 g3(NN/4, BB);
    k3_mixed<<<g3, 256>>>(ai, aj, aei, aej);

    const int kb_smem = (128*65 + 64*132) * 4;   // 67072 B
    cudaFuncSetAttribute((const void*)kB_gram,
                         cudaFuncAttributeMaxDynamicSharedMemorySize, kb_smem);
    dim3 gb(NN/128, NN/128, 10);
    kB_gram<<<gb, 256, kb_smem>>>();

    kC_topk<<<BB*NN/8, 256>>>();
    k6_gat<<<BB*NN/8, 256>>>(bgnn);
    k7_stats<<<128, 256>>>();
    k8_bnparam<<<1, 64>>>(0, g1, be1);
    k9_mid<<<128, 256>>>(emb);
    k8_bnparam<<<1, 64>>>(1, g2, be2);
    k11_out<<<BB*NN/8, 256>>>(Wout, bout, out, out_size);
}